// round 7
// baseline (speedup 1.0000x reference)
#include <cuda_runtime.h>
#include <cstdint>

#define NN   50000
#define EE   800000
#define FIN  64
#define HH   128
#define GG   16
#define NB   ((NN + 255) / 256)      // 196 scan blocks

// ---------------- device scratch (static allocation only) ----------------
__device__ int   g_cnt  [NN];                 // degree counts -> CSR cursor
__device__ int   g_rowptr[NN + 1];
__device__ int   g_bsum [NB];                 // per-block degree sums
__device__ int2  g_edge [EE];                 // {src, norm bits} sorted by dst
__device__ float g_dinv [NN];
__device__ float g_hw   [(size_t)NN * HH];    // h @ W
__device__ float g_h    [(size_t)NN * HH];    // activations between layers
__device__ float g_pool [GG * HH];
__device__ float g_gcnt [GG];

// ---------------- helpers ----------------
__device__ __forceinline__ void red_add_v4(float* addr, float4 v) {
    asm volatile("red.global.add.v4.f32 [%0], {%1,%2,%3,%4};"
                 :: "l"(addr), "f"(v.x), "f"(v.y), "f"(v.z), "f"(v.w)
                 : "memory");
}

// ---------------- precompute: zero counters / pool ----------------
__global__ void init_kernel() {
    int i = blockIdx.x * blockDim.x + threadIdx.x;
    if (i < NN) g_cnt[i] = 0;
    if (i < GG * HH) g_pool[i] = 0.f;
    if (i < GG) g_gcnt[i] = 0.f;
}

__global__ void gcnt_kernel(const int* __restrict__ batch) {
    int i = blockIdx.x * blockDim.x + threadIdx.x;
    if (i < NN) atomicAdd(&g_gcnt[batch[i]], 1.0f);
}

__global__ void deg_kernel(const int* __restrict__ dst) {
    int e = blockIdx.x * blockDim.x + threadIdx.x;
    if (e < EE) atomicAdd(&g_cnt[dst[e]], 1);
}

// ---- parallel scan, phase 1: per-block degree sums ----
__global__ __launch_bounds__(256) void scan_partial_kernel() {
    __shared__ int sm[256];
    int i = blockIdx.x * 256 + threadIdx.x;
    int t = threadIdx.x;
    sm[t] = (i < NN) ? g_cnt[i] : 0;
    __syncthreads();
#pragma unroll
    for (int s = 128; s > 0; s >>= 1) {
        if (t < s) sm[t] += sm[t + s];
        __syncthreads();
    }
    if (t == 0) g_bsum[blockIdx.x] = sm[0];
}

// ---- phase 2: exclusive scan of NB block sums (one block) ----
__global__ __launch_bounds__(256) void scan_bsum_kernel() {
    __shared__ int sm[256];
    int t = threadIdx.x;
    int v = (t < NB) ? g_bsum[t] : 0;
    sm[t] = v;
    __syncthreads();
#pragma unroll
    for (int s = 1; s < 256; s <<= 1) {
        int x = (t >= s) ? sm[t - s] : 0;
        __syncthreads();
        sm[t] += x;
        __syncthreads();
    }
    if (t < NB) g_bsum[t] = sm[t] - v;           // exclusive
}

// ---- phase 3: intra-block scan + offset -> rowptr, cursor, dinv ----
__global__ __launch_bounds__(256) void scan_apply_kernel() {
    __shared__ int sm[256];
    int i = blockIdx.x * 256 + threadIdx.x;
    int t = threadIdx.x;
    int deg = (i < NN) ? g_cnt[i] : 0;
    sm[t] = deg;
    __syncthreads();
#pragma unroll
    for (int s = 1; s < 256; s <<= 1) {
        int x = (t >= s) ? sm[t - s] : 0;
        __syncthreads();
        sm[t] += x;
        __syncthreads();
    }
    if (i < NN) {
        int off = g_bsum[blockIdx.x] + sm[t] - deg;   // exclusive prefix
        g_rowptr[i] = off;
        g_cnt[i]    = off;                             // cursor for fill
        g_dinv[i]   = rsqrtf((float)(deg + 1));        // +1 self loop
    }
    if (blockIdx.x == 0 && t == 0) g_rowptr[NN] = EE;
}

__global__ void fill_kernel(const int* __restrict__ src, const int* __restrict__ dst) {
    int e = blockIdx.x * blockDim.x + threadIdx.x;
    if (e >= EE) return;
    int   s  = src[e];
    int   d  = dst[e];
    float nv = g_dinv[s] * g_dinv[d];
    int   p  = atomicAdd(&g_cnt[d], 1);
    g_edge[p] = make_int2(s, __float_as_int(nv));
}

// ---------------- SGEMM: C[M,128] = A[M,K] @ B[K,128] ----------------
__global__ __launch_bounds__(256) void gemm_kernel(
    const float* __restrict__ A, const float* __restrict__ B,
    float* __restrict__ C, int M, int K)
{
    __shared__ float As[16][128];
    __shared__ float Bs[16][128];

    const int tid = threadIdx.x;
    const int tr  = tid >> 4;
    const int tc  = tid & 15;
    const int block_row = blockIdx.x * 128;

    float acc[8][8];
#pragma unroll
    for (int m = 0; m < 8; m++)
#pragma unroll
        for (int n = 0; n < 8; n++) acc[m][n] = 0.f;

    for (int k0 = 0; k0 < K; k0 += 16) {
#pragma unroll
        for (int i = 0; i < 2; i++) {
            int f   = tid + i * 256;
            int row = f >> 2;
            int c4  = (f & 3) * 4;
            int grow = block_row + row;
            float4 v = make_float4(0.f, 0.f, 0.f, 0.f);
            if (grow < M)
                v = *reinterpret_cast<const float4*>(A + (size_t)grow * K + k0 + c4);
            As[c4 + 0][row] = v.x;
            As[c4 + 1][row] = v.y;
            As[c4 + 2][row] = v.z;
            As[c4 + 3][row] = v.w;
        }
#pragma unroll
        for (int i = 0; i < 2; i++) {
            int f   = tid + i * 256;
            int row = f >> 5;
            int c4  = (f & 31) * 4;
            float4 v = *reinterpret_cast<const float4*>(B + (size_t)(k0 + row) * 128 + c4);
            *reinterpret_cast<float4*>(&Bs[row][c4]) = v;
        }
        __syncthreads();

#pragma unroll
        for (int k = 0; k < 16; k++) {
            float a[8], b[8];
#pragma unroll
            for (int m = 0; m < 8; m++) a[m] = As[k][tr * 8 + m];
#pragma unroll
            for (int n = 0; n < 8; n++) b[n] = Bs[k][tc * 8 + n];
#pragma unroll
            for (int m = 0; m < 8; m++)
#pragma unroll
                for (int n = 0; n < 8; n++) acc[m][n] = fmaf(a[m], b[n], acc[m][n]);
        }
        __syncthreads();
    }

#pragma unroll
    for (int m = 0; m < 8; m++) {
        int grow = block_row + tr * 8 + m;
        if (grow < M) {
#pragma unroll
            for (int n4 = 0; n4 < 2; n4++) {
                float4 v = make_float4(acc[m][n4 * 4 + 0], acc[m][n4 * 4 + 1],
                                       acc[m][n4 * 4 + 2], acc[m][n4 * 4 + 3]);
                *reinterpret_cast<float4*>(C + (size_t)grow * 128 + tc * 8 + n4 * 4) = v;
            }
        }
    }
}

// ---------------- fused aggregate + self-loop + bias + relu (+pool) ----------
// one warp per destination node; register accumulation, no atomics
__global__ __launch_bounds__(256) void msg_fused_kernel(
    const float* __restrict__ bias, int do_relu, int do_pool,
    const int* __restrict__ batch)
{
    int gid  = blockIdx.x * blockDim.x + threadIdx.x;
    int i    = gid >> 5;
    int lane = gid & 31;
    if (i >= NN) return;

    int beg = __ldg(&g_rowptr[i]);
    int end = __ldg(&g_rowptr[i + 1]);

    float4 acc = make_float4(0.f, 0.f, 0.f, 0.f);
    int e = beg;
    for (; e + 1 < end; e += 2) {
        int2 p0 = __ldg(&g_edge[e]);
        int2 p1 = __ldg(&g_edge[e + 1]);
        float n0 = __int_as_float(p0.y);
        float n1 = __int_as_float(p1.y);
        float4 v0 = *reinterpret_cast<const float4*>(&g_hw[(size_t)p0.x * 128 + lane * 4]);
        float4 v1 = *reinterpret_cast<const float4*>(&g_hw[(size_t)p1.x * 128 + lane * 4]);
        acc.x = fmaf(v0.x, n0, acc.x); acc.y = fmaf(v0.y, n0, acc.y);
        acc.z = fmaf(v0.z, n0, acc.z); acc.w = fmaf(v0.w, n0, acc.w);
        acc.x = fmaf(v1.x, n1, acc.x); acc.y = fmaf(v1.y, n1, acc.y);
        acc.z = fmaf(v1.z, n1, acc.z); acc.w = fmaf(v1.w, n1, acc.w);
    }
    if (e < end) {
        int2 p0 = __ldg(&g_edge[e]);
        float n0 = __int_as_float(p0.y);
        float4 v0 = *reinterpret_cast<const float4*>(&g_hw[(size_t)p0.x * 128 + lane * 4]);
        acc.x = fmaf(v0.x, n0, acc.x); acc.y = fmaf(v0.y, n0, acc.y);
        acc.z = fmaf(v0.z, n0, acc.z); acc.w = fmaf(v0.w, n0, acc.w);
    }

    float dn = __ldg(&g_dinv[i]);
    float sn = dn * dn;                            // self-loop norm
    float4 hs = *reinterpret_cast<const float4*>(&g_hw[(size_t)i * 128 + lane * 4]);
    float4 b  = *reinterpret_cast<const float4*>(bias + lane * 4);

    float4 r;
    r.x = fmaf(hs.x, sn, acc.x) + b.x;
    r.y = fmaf(hs.y, sn, acc.y) + b.y;
    r.z = fmaf(hs.z, sn, acc.z) + b.z;
    r.w = fmaf(hs.w, sn, acc.w) + b.w;
    if (do_relu) {
        r.x = fmaxf(r.x, 0.f); r.y = fmaxf(r.y, 0.f);
        r.z = fmaxf(r.z, 0.f); r.w = fmaxf(r.w, 0.f);
    }
    *reinterpret_cast<float4*>(&g_h[(size_t)i * 128 + lane * 4]) = r;

    if (do_pool) {
        int g = __ldg(&batch[i]);
        red_add_v4(&g_pool[g * 128 + lane * 4], r);
    }
}

// ---------------- MLP head (single block) ----------------
__global__ __launch_bounds__(256) void mlp_kernel(
    const float* __restrict__ lw1, const float* __restrict__ lb1,
    const float* __restrict__ lw2, const float* __restrict__ lb2,
    float* __restrict__ out)
{
    __shared__ float p[GG][HH];
    __shared__ float mid[GG][64];
    int t = threadIdx.x;

    for (int i = t; i < GG * HH; i += 256) {
        int g = i / HH;
        p[g][i % HH] = g_pool[i] / fmaxf(g_gcnt[g], 1.0f);
    }
    __syncthreads();

    for (int i = t; i < GG * 64; i += 256) {
        int g = i / 64, j = i % 64;
        float s = lb1[j];
#pragma unroll 8
        for (int k = 0; k < 128; k++) s = fmaf(p[g][k], lw1[k * 64 + j], s);
        mid[g][j] = fmaxf(s, 0.f);
    }
    __syncthreads();

    if (t < GG * 2) {
        int g = t >> 1, c = t & 1;
        float s = lb2[c];
#pragma unroll 8
        for (int k = 0; k < 64; k++) s = fmaf(mid[g][k], lw2[k * 2 + c], s);
        out[g * 2 + c] = s;
    }
}

// ---------------- host launcher ----------------
extern "C" void kernel_launch(void* const* d_in, const int* in_sizes, int n_in,
                              void* d_out, int out_size)
{
    const float* x    = (const float*)d_in[0];
    const int*   ei   = (const int*)  d_in[1];
    const int*   batch= (const int*)  d_in[2];
    const float* W1 = (const float*)d_in[3];  const float* b1 = (const float*)d_in[4];
    const float* W2 = (const float*)d_in[5];  const float* b2 = (const float*)d_in[6];
    const float* W3 = (const float*)d_in[7];  const float* b3 = (const float*)d_in[8];
    const float* W4 = (const float*)d_in[9];  const float* b4 = (const float*)d_in[10];
    const float* lw1= (const float*)d_in[11]; const float* lb1= (const float*)d_in[12];
    const float* lw2= (const float*)d_in[13]; const float* lb2= (const float*)d_in[14];
    float* out = (float*)d_out;

    const int* src = ei;        // edge_index[0]  (message source)
    const int* dst = ei + EE;   // edge_index[1]  (aggregation target)

    float *p_hw, *p_h;
    cudaGetSymbolAddress((void**)&p_hw, g_hw);
    cudaGetSymbolAddress((void**)&p_h,  g_h);

    // ---- CSR build + normalization (once, reused by all 4 layers) ----
    init_kernel        <<<(NN + 255) / 256, 256>>>();
    gcnt_kernel        <<<(NN + 255) / 256, 256>>>(batch);
    deg_kernel         <<<(EE + 255) / 256, 256>>>(dst);
    scan_partial_kernel<<<NB, 256>>>();
    scan_bsum_kernel   <<<1, 256>>>();
    scan_apply_kernel  <<<NB, 256>>>();
    fill_kernel        <<<(EE + 255) / 256, 256>>>(src, dst);

    const int gemm_blocks = (NN + 127) / 128;
    const int msg_blocks  = (NN * 32 + 255) / 256;

    struct Layer { const float* W; const float* b; int K; int relu; int pool; };
    const Layer layers[4] = {
        { W1, b1, FIN, 1, 0 }, { W2, b2, HH, 1, 0 },
        { W3, b3, HH,  1, 0 }, { W4, b4, HH, 0, 1 }
    };

    const float* h_in = x;
    for (int L = 0; L < 4; L++) {
        gemm_kernel     <<<gemm_blocks, 256>>>(h_in, layers[L].W, p_hw, NN, layers[L].K);
        msg_fused_kernel<<<msg_blocks, 256>>>(layers[L].b, layers[L].relu,
                                              layers[L].pool, batch);
        h_in = p_h;
    }

    mlp_kernel<<<1, 256>>>(lw1, lb1, lw2, lb2, out);
}

// round 9
// speedup vs baseline: 1.3711x; 1.3711x over previous
#include <cuda_runtime.h>
#include <cstdint>

#define NN   50000
#define EE   800000
#define FIN  64
#define HH   128
#define GG   16
#define NB   ((NN + 255) / 256)      // 196 scan blocks

// ---------------- device scratch (static allocation only) ----------------
__device__ int   g_cnt  [NN];                 // degree counts -> CSR cursor
__device__ int   g_rowptr[NN + 1];
__device__ int   g_bsum [NB];                 // per-block degree sums
__device__ int2  g_edge [EE];                 // {src, norm bits} sorted by dst
__device__ float g_dinv [NN];
__device__ __align__(16) float g_hw  [(size_t)NN * HH];    // h @ W
__device__ __align__(16) float g_h   [(size_t)NN * HH];    // activations
__device__ float g_pool [GG * HH];
__device__ float g_gcnt [GG];

// ---------------- helpers ----------------
__device__ __forceinline__ void red_add_v4(float* addr, float4 v) {
    asm volatile("red.global.add.v4.f32 [%0], {%1,%2,%3,%4};"
                 :: "l"(addr), "f"(v.x), "f"(v.y), "f"(v.z), "f"(v.w)
                 : "memory");
}

// packed fp32x2 FMA (sm_100+ baseline PTX; SASS FFMA2 — 2x fp32 rate)
__device__ __forceinline__ void fma2(unsigned long long& d,
                                     unsigned long long a, unsigned long long b) {
    asm("fma.rn.f32x2 %0, %1, %2, %3;" : "=l"(d) : "l"(a), "l"(b), "l"(d));
}
__device__ __forceinline__ unsigned long long dup2(float x) {
    unsigned long long r;
    asm("mov.b64 %0, {%1, %1};" : "=l"(r) : "f"(x));
    return r;
}
__device__ __forceinline__ float2 unpk2(unsigned long long v) {
    float2 r;
    asm("mov.b64 {%0, %1}, %2;" : "=f"(r.x), "=f"(r.y) : "l"(v));
    return r;
}

// ---------------- precompute ----------------
__global__ void init_kernel() {
    int i = blockIdx.x * blockDim.x + threadIdx.x;
    if (i < NN) g_cnt[i] = 0;
    if (i < GG * HH) g_pool[i] = 0.f;
    if (i < GG) g_gcnt[i] = 0.f;
}

__global__ void gcnt_kernel(const int* __restrict__ batch) {
    int i = blockIdx.x * blockDim.x + threadIdx.x;
    if (i < NN) atomicAdd(&g_gcnt[batch[i]], 1.0f);
}

__global__ void deg_kernel(const int* __restrict__ dst) {
    int e = blockIdx.x * blockDim.x + threadIdx.x;
    if (e < EE) atomicAdd(&g_cnt[dst[e]], 1);
}

__global__ __launch_bounds__(256) void scan_partial_kernel() {
    __shared__ int sm[256];
    int i = blockIdx.x * 256 + threadIdx.x;
    int t = threadIdx.x;
    sm[t] = (i < NN) ? g_cnt[i] : 0;
    __syncthreads();
#pragma unroll
    for (int s = 128; s > 0; s >>= 1) {
        if (t < s) sm[t] += sm[t + s];
        __syncthreads();
    }
    if (t == 0) g_bsum[blockIdx.x] = sm[0];
}

__global__ __launch_bounds__(256) void scan_bsum_kernel() {
    __shared__ int sm[256];
    int t = threadIdx.x;
    int v = (t < NB) ? g_bsum[t] : 0;
    sm[t] = v;
    __syncthreads();
#pragma unroll
    for (int s = 1; s < 256; s <<= 1) {
        int x = (t >= s) ? sm[t - s] : 0;
        __syncthreads();
        sm[t] += x;
        __syncthreads();
    }
    if (t < NB) g_bsum[t] = sm[t] - v;           // exclusive
}

__global__ __launch_bounds__(256) void scan_apply_kernel() {
    __shared__ int sm[256];
    int i = blockIdx.x * 256 + threadIdx.x;
    int t = threadIdx.x;
    int deg = (i < NN) ? g_cnt[i] : 0;
    sm[t] = deg;
    __syncthreads();
#pragma unroll
    for (int s = 1; s < 256; s <<= 1) {
        int x = (t >= s) ? sm[t - s] : 0;
        __syncthreads();
        sm[t] += x;
        __syncthreads();
    }
    if (i < NN) {
        int off = g_bsum[blockIdx.x] + sm[t] - deg;   // exclusive prefix
        g_rowptr[i] = off;
        g_cnt[i]    = off;                             // cursor for fill
        g_dinv[i]   = rsqrtf((float)(deg + 1));        // +1 self loop
    }
    if (blockIdx.x == 0 && t == 0) g_rowptr[NN] = EE;
}

__global__ void fill_kernel(const int* __restrict__ src, const int* __restrict__ dst) {
    int e = blockIdx.x * blockDim.x + threadIdx.x;
    if (e >= EE) return;
    int   s  = src[e];
    int   d  = dst[e];
    float nv = g_dinv[s] * g_dinv[d];
    int   p  = atomicAdd(&g_cnt[d], 1);
    g_edge[p] = make_int2(s, __float_as_int(nv));
}

// ---------------- SGEMM (FFMA2): C[M,128] = A[M,K] @ B[K,128] ----------------
// BM=128, BN=128, BK=16, thread tile 8x8 as 8x(4 float2), 256 threads
__global__ __launch_bounds__(256) void gemm_kernel(
    const float* __restrict__ A, const float* __restrict__ B,
    float* __restrict__ C, int M, int K)
{
    __shared__ float As[16][128];
    __shared__ float Bs[16][128];

    const int tid = threadIdx.x;
    const int tr  = tid >> 4;          // 0..15
    const int tc  = tid & 15;          // 0..15
    const int block_row = blockIdx.x * 128;

    unsigned long long acc[8][4];
#pragma unroll
    for (int m = 0; m < 8; m++)
#pragma unroll
        for (int n = 0; n < 4; n++) acc[m][n] = 0ull;

    for (int k0 = 0; k0 < K; k0 += 16) {
        // load A tile (128 x 16) transposed into As[k][row]
#pragma unroll
        for (int i = 0; i < 2; i++) {
            int f   = tid + i * 256;
            int row = f >> 2;
            int c4  = (f & 3) * 4;
            int grow = block_row + row;
            float4 v = make_float4(0.f, 0.f, 0.f, 0.f);
            if (grow < M)
                v = *reinterpret_cast<const float4*>(A + (size_t)grow * K + k0 + c4);
            As[c4 + 0][row] = v.x;
            As[c4 + 1][row] = v.y;
            As[c4 + 2][row] = v.z;
            As[c4 + 3][row] = v.w;
        }
        // load B tile (16 x 128)
#pragma unroll
        for (int i = 0; i < 2; i++) {
            int f   = tid + i * 256;
            int row = f >> 5;
            int c4  = (f & 31) * 4;
            float4 v = *reinterpret_cast<const float4*>(B + (size_t)(k0 + row) * 128 + c4);
            *reinterpret_cast<float4*>(&Bs[row][c4]) = v;
        }
        __syncthreads();

#pragma unroll
        for (int k = 0; k < 16; k++) {
            float4 a03 = *reinterpret_cast<const float4*>(&As[k][tr * 8]);
            float4 a47 = *reinterpret_cast<const float4*>(&As[k][tr * 8 + 4]);
            ulonglong2 b01 = *reinterpret_cast<const ulonglong2*>(&Bs[k][tc * 8]);
            ulonglong2 b23 = *reinterpret_cast<const ulonglong2*>(&Bs[k][tc * 8 + 4]);
            unsigned long long bb[4] = { b01.x, b01.y, b23.x, b23.y };
            float av[8] = { a03.x, a03.y, a03.z, a03.w, a47.x, a47.y, a47.z, a47.w };
#pragma unroll
            for (int m = 0; m < 8; m++) {
                unsigned long long a2 = dup2(av[m]);
#pragma unroll
                for (int n = 0; n < 4; n++) fma2(acc[m][n], a2, bb[n]);
            }
        }
        __syncthreads();
    }

    // writeback
#pragma unroll
    for (int m = 0; m < 8; m++) {
        int grow = block_row + tr * 8 + m;
        if (grow < M) {
            float2 r0 = unpk2(acc[m][0]);
            float2 r1 = unpk2(acc[m][1]);
            float2 r2 = unpk2(acc[m][2]);
            float2 r3 = unpk2(acc[m][3]);
            float4* cp = reinterpret_cast<float4*>(C + (size_t)grow * 128 + tc * 8);
            cp[0] = make_float4(r0.x, r0.y, r1.x, r1.y);
            cp[1] = make_float4(r2.x, r2.y, r3.x, r3.y);
        }
    }
}

// ---------------- fused aggregate + self-loop + bias + relu (+pool) ----------
// one warp per destination node; register accumulation, no atomics
__global__ __launch_bounds__(256) void msg_fused_kernel(
    const float* __restrict__ bias, int do_relu, int do_pool,
    const int* __restrict__ batch)
{
    int gid  = blockIdx.x * blockDim.x + threadIdx.x;
    int i    = gid >> 5;
    int lane = gid & 31;
    if (i >= NN) return;

    int beg = __ldg(&g_rowptr[i]);
    int end = __ldg(&g_rowptr[i + 1]);

    float4 acc = make_float4(0.f, 0.f, 0.f, 0.f);
    int e = beg;
    for (; e + 1 < end; e += 2) {
        int2 p0 = __ldg(&g_edge[e]);
        int2 p1 = __ldg(&g_edge[e + 1]);
        float n0 = __int_as_float(p0.y);
        float n1 = __int_as_float(p1.y);
        float4 v0 = *reinterpret_cast<const float4*>(&g_hw[(size_t)p0.x * 128 + lane * 4]);
        float4 v1 = *reinterpret_cast<const float4*>(&g_hw[(size_t)p1.x * 128 + lane * 4]);
        acc.x = fmaf(v0.x, n0, acc.x); acc.y = fmaf(v0.y, n0, acc.y);
        acc.z = fmaf(v0.z, n0, acc.z); acc.w = fmaf(v0.w, n0, acc.w);
        acc.x = fmaf(v1.x, n1, acc.x); acc.y = fmaf(v1.y, n1, acc.y);
        acc.z = fmaf(v1.z, n1, acc.z); acc.w = fmaf(v1.w, n1, acc.w);
    }
    if (e < end) {
        int2 p0 = __ldg(&g_edge[e]);
        float n0 = __int_as_float(p0.y);
        float4 v0 = *reinterpret_cast<const float4*>(&g_hw[(size_t)p0.x * 128 + lane * 4]);
        acc.x = fmaf(v0.x, n0, acc.x); acc.y = fmaf(v0.y, n0, acc.y);
        acc.z = fmaf(v0.z, n0, acc.z); acc.w = fmaf(v0.w, n0, acc.w);
    }

    float dn = __ldg(&g_dinv[i]);
    float sn = dn * dn;                            // self-loop norm
    float4 hs = *reinterpret_cast<const float4*>(&g_hw[(size_t)i * 128 + lane * 4]);
    float4 b  = *reinterpret_cast<const float4*>(bias + lane * 4);

    float4 r;
    r.x = fmaf(hs.x, sn, acc.x) + b.x;
    r.y = fmaf(hs.y, sn, acc.y) + b.y;
    r.z = fmaf(hs.z, sn, acc.z) + b.z;
    r.w = fmaf(hs.w, sn, acc.w) + b.w;
    if (do_relu) {
        r.x = fmaxf(r.x, 0.f); r.y = fmaxf(r.y, 0.f);
        r.z = fmaxf(r.z, 0.f); r.w = fmaxf(r.w, 0.f);
    }
    *reinterpret_cast<float4*>(&g_h[(size_t)i * 128 + lane * 4]) = r;

    if (do_pool) {
        int g = __ldg(&batch[i]);
        red_add_v4(&g_pool[g * 128 + lane * 4], r);
    }
}

// ---------------- MLP head (single block) ----------------
__global__ __launch_bounds__(256) void mlp_kernel(
    const float* __restrict__ lw1, const float* __restrict__ lb1,
    const float* __restrict__ lw2, const float* __restrict__ lb2,
    float* __restrict__ out)
{
    __shared__ float p[GG][HH];
    __shared__ float mid[GG][64];
    int t = threadIdx.x;

    for (int i = t; i < GG * HH; i += 256) {
        int g = i / HH;
        p[g][i % HH] = g_pool[i] / fmaxf(g_gcnt[g], 1.0f);
    }
    __syncthreads();

    for (int i = t; i < GG * 64; i += 256) {
        int g = i / 64, j = i % 64;
        float s = lb1[j];
#pragma unroll 8
        for (int k = 0; k < 128; k++) s = fmaf(p[g][k], lw1[k * 64 + j], s);
        mid[g][j] = fmaxf(s, 0.f);
    }
    __syncthreads();

    if (t < GG * 2) {
        int g = t >> 1, c = t & 1;
        float s = lb2[c];
#pragma unroll 8
        for (int k = 0; k < 64; k++) s = fmaf(mid[g][k], lw2[k * 2 + c], s);
        out[g * 2 + c] = s;
    }
}

// ---------------- host launcher ----------------
extern "C" void kernel_launch(void* const* d_in, const int* in_sizes, int n_in,
                              void* d_out, int out_size)
{
    const float* x    = (const float*)d_in[0];
    const int*   ei   = (const int*)  d_in[1];
    const int*   batch= (const int*)  d_in[2];
    const float* W1 = (const float*)d_in[3];  const float* b1 = (const float*)d_in[4];
    const float* W2 = (const float*)d_in[5];  const float* b2 = (const float*)d_in[6];
    const float* W3 = (const float*)d_in[7];  const float* b3 = (const float*)d_in[8];
    const float* W4 = (const float*)d_in[9];  const float* b4 = (const float*)d_in[10];
    const float* lw1= (const float*)d_in[11]; const float* lb1= (const float*)d_in[12];
    const float* lw2= (const float*)d_in[13]; const float* lb2= (const float*)d_in[14];
    float* out = (float*)d_out;

    const int* src = ei;        // edge_index[0]  (message source)
    const int* dst = ei + EE;   // edge_index[1]  (aggregation target)

    float *p_hw, *p_h;
    cudaGetSymbolAddress((void**)&p_hw, g_hw);
    cudaGetSymbolAddress((void**)&p_h,  g_h);

    const int gemm_blocks = (NN + 127) / 128;
    const int msg_blocks  = (NN * 32 + 255) / 256;

    // ---- CSR build + normalization; gemm1 placed 6th so ncu (-s 5) profiles it
    init_kernel        <<<(NN + 255) / 256, 256>>>();
    gcnt_kernel        <<<(NN + 255) / 256, 256>>>(batch);
    deg_kernel         <<<(EE + 255) / 256, 256>>>(dst);
    scan_partial_kernel<<<NB, 256>>>();
    scan_bsum_kernel   <<<1, 256>>>();
    gemm_kernel        <<<gemm_blocks, 256>>>(x, W1, p_hw, NN, FIN);   // launch #6
    scan_apply_kernel  <<<NB, 256>>>();
    fill_kernel        <<<(EE + 255) / 256, 256>>>(src, dst);

    struct Layer { const float* W; const float* b; int K; int relu; int pool; };
    const Layer layers[4] = {
        { W1, b1, FIN, 1, 0 }, { W2, b2, HH, 1, 0 },
        { W3, b3, HH,  1, 0 }, { W4, b4, HH, 0, 1 }
    };

    const float* h_in = x;
    for (int L = 0; L < 4; L++) {
        if (L > 0)
            gemm_kernel <<<gemm_blocks, 256>>>(h_in, layers[L].W, p_hw, NN, layers[L].K);
        msg_fused_kernel<<<msg_blocks, 256>>>(layers[L].b, layers[L].relu,
                                              layers[L].pool, batch);
        h_in = p_h;
    }

    mlp_kernel<<<1, 256>>>(lw1, lb1, lw2, lb2, out);
}

// round 11
// speedup vs baseline: 1.7275x; 1.2600x over previous
#include <cuda_runtime.h>
#include <cstdint>

#define NN   50000
#define EE   800000
#define FIN  64
#define HH   128
#define GG   16
#define NB   ((NN + 255) / 256)      // 196 scan blocks

// ---------------- device scratch (static allocation only) ----------------
// Invariants maintained across graph replays (zero-init at module load):
//   g_cnt  == 0 on entry (reset by msg_x_kernel after fill uses it as cursor)
//   g_pool == 0 on entry (zeroed by mlp_kernel after it reads the pool)
__device__ int   g_cnt  [NN];
__device__ int   g_rowptr[NN + 1];
__device__ int   g_bsum [NB];
__device__ int2  g_edge [EE];                              // {src, norm bits} by dst
__device__ float g_dinv [NN];
__device__ __align__(16) float g_a [(size_t)NN * HH];      // aggregated features
__device__ __align__(16) float g_h [(size_t)NN * HH];      // activations
__device__ float g_pool [GG * HH];

// ---------------- helpers ----------------
__device__ __forceinline__ void red_add_v4(float* addr, float4 v) {
    asm volatile("red.global.add.v4.f32 [%0], {%1,%2,%3,%4};"
                 :: "l"(addr), "f"(v.x), "f"(v.y), "f"(v.z), "f"(v.w)
                 : "memory");
}

// packed fp32x2 FMA (sm_100+ baseline PTX; SASS FFMA2 — 2x fp32 rate)
__device__ __forceinline__ void fma2(unsigned long long& d,
                                     unsigned long long a, unsigned long long b) {
    asm("fma.rn.f32x2 %0, %1, %2, %3;" : "=l"(d) : "l"(a), "l"(b), "l"(d));
}
__device__ __forceinline__ unsigned long long dup2(float x) {
    unsigned long long r;
    asm("mov.b64 %0, {%1, %1};" : "=l"(r) : "f"(x));
    return r;
}
__device__ __forceinline__ float2 unpk2(unsigned long long v) {
    float2 r;
    asm("mov.b64 {%0, %1}, %2;" : "=f"(r.x), "=f"(r.y) : "l"(v));
    return r;
}

// ---------------- CSR build ----------------
__global__ void deg_kernel(const int* __restrict__ dst) {
    int e = blockIdx.x * blockDim.x + threadIdx.x;
    if (e < EE) atomicAdd(&g_cnt[dst[e]], 1);    // g_cnt starts at 0 (invariant)
}

__global__ __launch_bounds__(256) void scan_partial_kernel() {
    __shared__ int sm[256];
    int i = blockIdx.x * 256 + threadIdx.x;
    int t = threadIdx.x;
    sm[t] = (i < NN) ? g_cnt[i] : 0;
    __syncthreads();
#pragma unroll
    for (int s = 128; s > 0; s >>= 1) {
        if (t < s) sm[t] += sm[t + s];
        __syncthreads();
    }
    if (t == 0) g_bsum[blockIdx.x] = sm[0];
}

// inclusive-scan bsum inside every block (redundant, cheap) + per-element scan
__global__ __launch_bounds__(256) void scan_apply_kernel() {
    __shared__ int sb[256];
    __shared__ int sm[256];
    int t = threadIdx.x;

    int bv = (t < NB) ? g_bsum[t] : 0;
    sb[t] = bv;
    __syncthreads();
#pragma unroll
    for (int s = 1; s < 256; s <<= 1) {
        int x = (t >= s) ? sb[t - s] : 0;
        __syncthreads();
        sb[t] += x;
        __syncthreads();
    }
    int block_off = (blockIdx.x == 0) ? 0 : sb[blockIdx.x - 1];

    int i = blockIdx.x * 256 + t;
    int deg = (i < NN) ? g_cnt[i] : 0;
    sm[t] = deg;
    __syncthreads();
#pragma unroll
    for (int s = 1; s < 256; s <<= 1) {
        int x = (t >= s) ? sm[t - s] : 0;
        __syncthreads();
        sm[t] += x;
        __syncthreads();
    }
    if (i < NN) {
        int off = block_off + sm[t] - deg;            // exclusive prefix
        g_rowptr[i] = off;
        g_cnt[i]    = off;                             // cursor for fill
        g_dinv[i]   = rsqrtf((float)(deg + 1));        // +1 self loop
    }
    if (blockIdx.x == 0 && t == 0) g_rowptr[NN] = EE;
}

__global__ void fill_kernel(const int* __restrict__ src, const int* __restrict__ dst) {
    int e = blockIdx.x * blockDim.x + threadIdx.x;
    if (e >= EE) return;
    int   s  = src[e];
    int   d  = dst[e];
    float nv = g_dinv[s] * g_dinv[d];
    int   p  = atomicAdd(&g_cnt[d], 1);
    g_edge[p] = make_int2(s, __float_as_int(nv));
}

// ---------------- layer-1 aggregation over x (64 features) ----------------
// warp per node, float2 per lane; also resets g_cnt (cursor residue) to 0.
__global__ __launch_bounds__(256) void msg_x_kernel(const float* __restrict__ x) {
    int gid  = blockIdx.x * blockDim.x + threadIdx.x;
    int i    = gid >> 5;
    int lane = gid & 31;
    if (i >= NN) return;
    if (lane == 0) g_cnt[i] = 0;                 // restore invariant for next replay

    int beg = __ldg(&g_rowptr[i]);
    int end = __ldg(&g_rowptr[i + 1]);

    float2 acc = make_float2(0.f, 0.f);
    int e = beg;
    for (; e + 1 < end; e += 2) {
        int2 p0 = __ldg(&g_edge[e]);
        int2 p1 = __ldg(&g_edge[e + 1]);
        float n0 = __int_as_float(p0.y);
        float n1 = __int_as_float(p1.y);
        float2 v0 = *reinterpret_cast<const float2*>(x + (size_t)p0.x * FIN + lane * 2);
        float2 v1 = *reinterpret_cast<const float2*>(x + (size_t)p1.x * FIN + lane * 2);
        acc.x = fmaf(v0.x, n0, acc.x); acc.y = fmaf(v0.y, n0, acc.y);
        acc.x = fmaf(v1.x, n1, acc.x); acc.y = fmaf(v1.y, n1, acc.y);
    }
    if (e < end) {
        int2 p0 = __ldg(&g_edge[e]);
        float n0 = __int_as_float(p0.y);
        float2 v0 = *reinterpret_cast<const float2*>(x + (size_t)p0.x * FIN + lane * 2);
        acc.x = fmaf(v0.x, n0, acc.x); acc.y = fmaf(v0.y, n0, acc.y);
    }

    float dn = __ldg(&g_dinv[i]);
    float sn = dn * dn;
    float2 xs = *reinterpret_cast<const float2*>(x + (size_t)i * FIN + lane * 2);
    acc.x = fmaf(xs.x, sn, acc.x);
    acc.y = fmaf(xs.y, sn, acc.y);
    *reinterpret_cast<float2*>(g_a + (size_t)i * FIN + lane * 2) = acc;
}

// ---------------- aggregation over h (128 features), optional pool sink ------
__global__ __launch_bounds__(256) void msg_h_kernel(int do_pool,
                                                    const int* __restrict__ batch) {
    int gid  = blockIdx.x * blockDim.x + threadIdx.x;
    int i    = gid >> 5;
    int lane = gid & 31;
    if (i >= NN) return;

    int beg = __ldg(&g_rowptr[i]);
    int end = __ldg(&g_rowptr[i + 1]);

    float4 acc = make_float4(0.f, 0.f, 0.f, 0.f);
    int e = beg;
    for (; e + 1 < end; e += 2) {
        int2 p0 = __ldg(&g_edge[e]);
        int2 p1 = __ldg(&g_edge[e + 1]);
        float n0 = __int_as_float(p0.y);
        float n1 = __int_as_float(p1.y);
        float4 v0 = *reinterpret_cast<const float4*>(&g_h[(size_t)p0.x * 128 + lane * 4]);
        float4 v1 = *reinterpret_cast<const float4*>(&g_h[(size_t)p1.x * 128 + lane * 4]);
        acc.x = fmaf(v0.x, n0, acc.x); acc.y = fmaf(v0.y, n0, acc.y);
        acc.z = fmaf(v0.z, n0, acc.z); acc.w = fmaf(v0.w, n0, acc.w);
        acc.x = fmaf(v1.x, n1, acc.x); acc.y = fmaf(v1.y, n1, acc.y);
        acc.z = fmaf(v1.z, n1, acc.z); acc.w = fmaf(v1.w, n1, acc.w);
    }
    if (e < end) {
        int2 p0 = __ldg(&g_edge[e]);
        float n0 = __int_as_float(p0.y);
        float4 v0 = *reinterpret_cast<const float4*>(&g_h[(size_t)p0.x * 128 + lane * 4]);
        acc.x = fmaf(v0.x, n0, acc.x); acc.y = fmaf(v0.y, n0, acc.y);
        acc.z = fmaf(v0.z, n0, acc.z); acc.w = fmaf(v0.w, n0, acc.w);
    }

    float dn = __ldg(&g_dinv[i]);
    float sn = dn * dn;
    float4 hs = *reinterpret_cast<const float4*>(&g_h[(size_t)i * 128 + lane * 4]);
    acc.x = fmaf(hs.x, sn, acc.x);
    acc.y = fmaf(hs.y, sn, acc.y);
    acc.z = fmaf(hs.z, sn, acc.z);
    acc.w = fmaf(hs.w, sn, acc.w);

    if (do_pool) {
        int g = __ldg(&batch[i]);
        red_add_v4(&g_pool[g * 128 + lane * 4], acc);   // layer-4: straight to pool
    } else {
        *reinterpret_cast<float4*>(&g_a[(size_t)i * 128 + lane * 4]) = acc;
    }
}

// ---------------- SGEMM (FFMA2): h = relu(a @ W + b) ----------------
// BM=128, BN=128, BK=16, thread tile 8x8 as 8x(4 float2), 256 threads
__global__ __launch_bounds__(256) void gemm_kernel(
    const float* __restrict__ A, const float* __restrict__ B,
    const float* __restrict__ bias, float* __restrict__ C, int M, int K)
{
    __shared__ float As[16][128];
    __shared__ float Bs[16][128];

    const int tid = threadIdx.x;
    const int tr  = tid >> 4;          // 0..15
    const int tc  = tid & 15;          // 0..15
    const int block_row = blockIdx.x * 128;

    unsigned long long acc[8][4];
#pragma unroll
    for (int m = 0; m < 8; m++)
#pragma unroll
        for (int n = 0; n < 4; n++) acc[m][n] = 0ull;

    for (int k0 = 0; k0 < K; k0 += 16) {
#pragma unroll
        for (int i = 0; i < 2; i++) {
            int f   = tid + i * 256;
            int row = f >> 2;
            int c4  = (f & 3) * 4;
            int grow = block_row + row;
            float4 v = make_float4(0.f, 0.f, 0.f, 0.f);
            if (grow < M)
                v = *reinterpret_cast<const float4*>(A + (size_t)grow * K + k0 + c4);
            As[c4 + 0][row] = v.x;
            As[c4 + 1][row] = v.y;
            As[c4 + 2][row] = v.z;
            As[c4 + 3][row] = v.w;
        }
#pragma unroll
        for (int i = 0; i < 2; i++) {
            int f   = tid + i * 256;
            int row = f >> 5;
            int c4  = (f & 31) * 4;
            float4 v = *reinterpret_cast<const float4*>(B + (size_t)(k0 + row) * 128 + c4);
            *reinterpret_cast<float4*>(&Bs[row][c4]) = v;
        }
        __syncthreads();

#pragma unroll
        for (int k = 0; k < 16; k++) {
            float4 a03 = *reinterpret_cast<const float4*>(&As[k][tr * 8]);
            float4 a47 = *reinterpret_cast<const float4*>(&As[k][tr * 8 + 4]);
            ulonglong2 b01 = *reinterpret_cast<const ulonglong2*>(&Bs[k][tc * 8]);
            ulonglong2 b23 = *reinterpret_cast<const ulonglong2*>(&Bs[k][tc * 8 + 4]);
            unsigned long long bb[4] = { b01.x, b01.y, b23.x, b23.y };
            float av[8] = { a03.x, a03.y, a03.z, a03.w, a47.x, a47.y, a47.z, a47.w };
#pragma unroll
            for (int m = 0; m < 8; m++) {
                unsigned long long a2 = dup2(av[m]);
#pragma unroll
                for (int n = 0; n < 4; n++) fma2(acc[m][n], a2, bb[n]);
            }
        }
        __syncthreads();
    }

    // epilogue: + bias, relu
    float4 bv0 = *reinterpret_cast<const float4*>(bias + tc * 8);
    float4 bv1 = *reinterpret_cast<const float4*>(bias + tc * 8 + 4);
#pragma unroll
    for (int m = 0; m < 8; m++) {
        int grow = block_row + tr * 8 + m;
        if (grow < M) {
            float2 r0 = unpk2(acc[m][0]);
            float2 r1 = unpk2(acc[m][1]);
            float2 r2 = unpk2(acc[m][2]);
            float2 r3 = unpk2(acc[m][3]);
            float4 o0 = make_float4(fmaxf(r0.x + bv0.x, 0.f), fmaxf(r0.y + bv0.y, 0.f),
                                    fmaxf(r1.x + bv0.z, 0.f), fmaxf(r1.y + bv0.w, 0.f));
            float4 o1 = make_float4(fmaxf(r2.x + bv1.x, 0.f), fmaxf(r2.y + bv1.y, 0.f),
                                    fmaxf(r3.x + bv1.z, 0.f), fmaxf(r3.y + bv1.w, 0.f));
            float4* cp = reinterpret_cast<float4*>(C + (size_t)grow * 128 + tc * 8);
            cp[0] = o0;
            cp[1] = o1;
        }
    }
}

// ---------------- head: W4 + bias + MLP; zeroes g_pool after use ----------------
__device__ __forceinline__ int lower_bound_batch(const int* b, int key) {
    int lo = 0, hi = NN;
    while (lo < hi) {
        int mid = (lo + hi) >> 1;
        if (b[mid] < key) lo = mid + 1; else hi = mid;
    }
    return lo;
}

__global__ __launch_bounds__(256) void mlp_kernel(
    const float* __restrict__ W4, const float* __restrict__ b4,
    const float* __restrict__ lw1, const float* __restrict__ lb1,
    const float* __restrict__ lw2, const float* __restrict__ lb2,
    const int* __restrict__ batch, float* __restrict__ out)
{
    __shared__ float pa [GG][HH];
    __shared__ float h4 [GG][HH];
    __shared__ float mid[GG][64];
    __shared__ float cnt[GG];
    int t = threadIdx.x;

    if (t < GG) {
        int lo = lower_bound_batch(batch, t);
        int hi = lower_bound_batch(batch, t + 1);
        cnt[t] = fmaxf((float)(hi - lo), 1.0f);
    }
    for (int i = t; i < GG * HH; i += 256) {
        pa[i / HH][i % HH] = g_pool[i];
        g_pool[i] = 0.f;                       // restore invariant for next replay
    }
    __syncthreads();
    for (int i = t; i < GG * HH; i += 256)
        pa[i / HH][i % HH] /= cnt[i / HH];
    __syncthreads();

    // h4 = pa @ W4 + b4    (16 x 128, K=128) — 8 outputs per thread
    {
        int g  = t >> 4;
        int nb = (t & 15) * 8;
        float s[8];
#pragma unroll
        for (int j = 0; j < 8; j++) s[j] = b4[nb + j];
        for (int k = 0; k < 128; k++) {
            float a = pa[g][k];
            const float* wr = W4 + (size_t)k * 128 + nb;
#pragma unroll
            for (int j = 0; j < 8; j++) s[j] = fmaf(a, wr[j], s[j]);
        }
#pragma unroll
        for (int j = 0; j < 8; j++) h4[g][nb + j] = s[j];
    }
    __syncthreads();

    // mid = relu(h4 @ lw1 + lb1)    (16 x 64, K=128) — 4 outputs per thread
    {
        int g  = t >> 4;
        int jb = (t & 15) * 4;
        float s[4];
#pragma unroll
        for (int j = 0; j < 4; j++) s[j] = lb1[jb + j];
        for (int k = 0; k < 128; k++) {
            float a = h4[g][k];
            const float* wr = lw1 + (size_t)k * 64 + jb;
#pragma unroll
            for (int j = 0; j < 4; j++) s[j] = fmaf(a, wr[j], s[j]);
        }
#pragma unroll
        for (int j = 0; j < 4; j++) mid[g][jb + j] = fmaxf(s[j], 0.f);
    }
    __syncthreads();

    if (t < GG * 2) {
        int g = t >> 1, c = t & 1;
        float s = lb2[c];
#pragma unroll 8
        for (int k = 0; k < 64; k++) s = fmaf(mid[g][k], lw2[k * 2 + c], s);
        out[g * 2 + c] = s;
    }
}

// ---------------- host launcher ----------------
extern "C" void kernel_launch(void* const* d_in, const int* in_sizes, int n_in,
                              void* d_out, int out_size)
{
    const float* x    = (const float*)d_in[0];
    const int*   ei   = (const int*)  d_in[1];
    const int*   batch= (const int*)  d_in[2];
    const float* W1 = (const float*)d_in[3];  const float* b1 = (const float*)d_in[4];
    const float* W2 = (const float*)d_in[5];  const float* b2 = (const float*)d_in[6];
    const float* W3 = (const float*)d_in[7];  const float* b3 = (const float*)d_in[8];
    const float* W4 = (const float*)d_in[9];  const float* b4 = (const float*)d_in[10];
    const float* lw1= (const float*)d_in[11]; const float* lb1= (const float*)d_in[12];
    const float* lw2= (const float*)d_in[13]; const float* lb2= (const float*)d_in[14];
    float* out = (float*)d_out;

    const int* src = ei;        // edge_index[0]  (message source)
    const int* dst = ei + EE;   // edge_index[1]  (aggregation target)

    float *p_a, *p_h;
    cudaGetSymbolAddress((void**)&p_a, g_a);
    cudaGetSymbolAddress((void**)&p_h, g_h);

    const int gemm_blocks = (NN + 127) / 128;
    const int msg_blocks  = (NN * 32 + 255) / 256;

    // ---- CSR build (g_cnt invariant: zero on entry) ----
    deg_kernel         <<<(EE + 255) / 256, 256>>>(dst);       // 1
    scan_partial_kernel<<<NB, 256>>>();                        // 2
    scan_apply_kernel  <<<NB, 256>>>();                        // 3 (incl. bsum scan)
    fill_kernel        <<<(EE + 255) / 256, 256>>>(src, dst);  // 4

    // ---- layer 1: agg(x) -> gemm(relu) ----
    msg_x_kernel<<<msg_blocks, 256>>>(x);                                   // 5
    gemm_kernel <<<gemm_blocks, 256>>>(p_a, W1, b1, p_h, NN, FIN);          // 6
    // ---- layers 2,3: agg(h) -> gemm(relu) ----
    msg_h_kernel<<<msg_blocks, 256>>>(0, batch);                            // 7
    gemm_kernel <<<gemm_blocks, 256>>>(p_a, W2, b2, p_h, NN, HH);           // 8
    msg_h_kernel<<<msg_blocks, 256>>>(0, batch);                            // 9
    gemm_kernel <<<gemm_blocks, 256>>>(p_a, W3, b3, p_h, NN, HH);           // 10
    // ---- layer 4: agg(h3) pooled directly; W4+b4 folded into head ----
    msg_h_kernel<<<msg_blocks, 256>>>(1, batch);                            // 11
    mlp_kernel  <<<1, 256>>>(W4, b4, lw1, lb1, lw2, lb2, batch, out);       // 12
}